// round 12
// baseline (speedup 1.0000x reference)
#include <cuda_runtime.h>
#include <cuda_fp16.h>
#include <cstdint>

// ---------------------------------------------------------------------------
// PerceiverAttention — mma.sync fp16 hi/lo GEMMs (mixed 2/3-pass)
//                      + f32x2 split-KV attention
//   B=8, M=4096, N=256, DIM=1024, HEADS=16, DH=64, J=4352, INNER=1024
// ---------------------------------------------------------------------------

#define B_     8
#define M_     4096
#define N_     256
#define D_     1024
#define H_     16
#define J_     (M_ + N_)      // 4352
#define INNER_ 1024
#define SPLITS 4
#define JSPLIT (J_ / SPLITS)  // 1088

// ---------------- static device scratch -------------------------------------
__device__ __half g_ah  [(size_t)B_ * J_ * D_];
__device__ __half g_al  [(size_t)B_ * J_ * D_];
__device__ __half g_lath[(size_t)B_ * N_ * D_];
__device__ __half g_latl[(size_t)B_ * N_ * D_];
__device__ float  g_kv  [(size_t)B_ * J_ * 2 * INNER_];
__device__ float  g_q   [(size_t)B_ * N_ * INNER_];
__device__ __half g_atth[(size_t)B_ * N_ * INNER_];
__device__ __half g_attl[(size_t)B_ * N_ * INNER_];
__device__ __half g_wkvh[(size_t)2 * INNER_ * D_];
__device__ __half g_wkvl[(size_t)2 * INNER_ * D_];
__device__ __half g_wqh [(size_t)INNER_ * D_];
__device__ __half g_wql [(size_t)INNER_ * D_];
__device__ __half g_woh [(size_t)INNER_ * D_];
__device__ __half g_wol [(size_t)INNER_ * D_];
__device__ float  g_pacc[(size_t)SPLITS * B_ * N_ * INNER_];
__device__ float  g_pl  [(size_t)SPLITS * B_ * N_ * H_];

// ---------------- PTX helpers (plain sm_103-legal) ---------------------------
__device__ __forceinline__ unsigned su32(const void* p) {
    unsigned a;
    asm("{ .reg .u64 t; cvta.to.shared.u64 t, %1; cvt.u32.u64 %0, t; }"
        : "=r"(a) : "l"(p));
    return a;
}

#define CPA16(saddr, gptr) \
    asm volatile("cp.async.cg.shared.global [%0], [%1], 16;" \
                 :: "r"(saddr), "l"(gptr))
#define CPA_COMMIT() asm volatile("cp.async.commit_group;" ::: "memory")
#define CPA_WAIT1()  asm volatile("cp.async.wait_group 1;" ::: "memory")
#define CPA_WAIT0()  asm volatile("cp.async.wait_group 0;" ::: "memory")

#define LDSM4(r, addr) \
    asm volatile("ldmatrix.sync.aligned.m8n8.x4.shared.b16 {%0,%1,%2,%3}, [%4];" \
        : "=r"((r)[0]), "=r"((r)[1]), "=r"((r)[2]), "=r"((r)[3]) : "r"(addr))

#define MMA16816(c, a, b0, b1) \
    asm volatile("mma.sync.aligned.m16n8k16.row.col.f32.f16.f16.f32 " \
        "{%0,%1,%2,%3}, {%4,%5,%6,%7}, {%8,%9}, {%0,%1,%2,%3};" \
        : "+f"((c)[0]), "+f"((c)[1]), "+f"((c)[2]), "+f"((c)[3]) \
        : "r"((a)[0]), "r"((a)[1]), "r"((a)[2]), "r"((a)[3]), "r"(b0), "r"(b1))

// f32x2 packed fma (sm_103a)
#define FMA2(d, a, b, c) \
    asm("fma.rn.f32x2 %0, %1, %2, %3;" : "=l"(d) : "l"(a), "l"(b), "l"(c))

// ---------------------------------------------------------------------------
// LayerNorm -> fp16 hi/lo (kvin layout + optional compact latent copy)
// ---------------------------------------------------------------------------
__global__ void __launch_bounds__(256) ln_kernel(
    const float* __restrict__ x, const float* __restrict__ g,
    const float* __restrict__ be,
    __half* __restrict__ hi, __half* __restrict__ lo,
    int rpb, int base,
    __half* __restrict__ hi2, __half* __restrict__ lo2)
{
    int row = blockIdx.x;
    int tid = threadIdx.x;

    const float4* xr = reinterpret_cast<const float4*>(x) + (size_t)row * 256;
    float4 v = xr[tid];
    float s  = v.x + v.y + v.z + v.w;
    float ss = v.x * v.x + v.y * v.y + v.z * v.z + v.w * v.w;
    #pragma unroll
    for (int o = 16; o > 0; o >>= 1) {
        s  += __shfl_xor_sync(0xffffffffu, s,  o);
        ss += __shfl_xor_sync(0xffffffffu, ss, o);
    }
    __shared__ float ssum[8], ssq[8], sstat[2];
    int wid = tid >> 5, lid = tid & 31;
    if (lid == 0) { ssum[wid] = s; ssq[wid] = ss; }
    __syncthreads();
    if (tid == 0) {
        float a = 0.f, q2 = 0.f;
        #pragma unroll
        for (int i = 0; i < 8; i++) { a += ssum[i]; q2 += ssq[i]; }
        float mu  = a * (1.0f / 1024.0f);
        float var = q2 * (1.0f / 1024.0f) - mu * mu;
        sstat[0] = mu;
        sstat[1] = rsqrtf(var + 1e-5f);
    }
    __syncthreads();
    float mu = sstat[0], rs = sstat[1];

    float4 gv = reinterpret_cast<const float4*>(g)[tid];
    float4 bv = reinterpret_cast<const float4*>(be)[tid];
    float o0 = (v.x - mu) * rs * gv.x + bv.x;
    float o1 = (v.y - mu) * rs * gv.y + bv.y;
    float o2 = (v.z - mu) * rs * gv.z + bv.z;
    float o3 = (v.w - mu) * rs * gv.w + bv.w;

    __half h0 = __float2half_rn(o0);
    __half h1 = __float2half_rn(o1);
    __half h2 = __float2half_rn(o2);
    __half h3 = __float2half_rn(o3);
    __half l0 = __float2half_rn(o0 - __half2float(h0));
    __half l1 = __float2half_rn(o1 - __half2float(h1));
    __half l2 = __float2half_rn(o2 - __half2float(h2));
    __half l3 = __float2half_rn(o3 - __half2float(h3));
    __half2 hp0 = __halves2half2(h0, h1), hp1 = __halves2half2(h2, h3);
    __half2 lp0 = __halves2half2(l0, l1), lp1 = __halves2half2(l2, l3);

    int b = row / rpb;
    int r = row - b * rpb;
    size_t off = ((size_t)b * J_ + base + r) * 1024 + tid * 4;
    *reinterpret_cast<__half2*>(hi + off)     = hp0;
    *reinterpret_cast<__half2*>(hi + off + 2) = hp1;
    *reinterpret_cast<__half2*>(lo + off)     = lp0;
    *reinterpret_cast<__half2*>(lo + off + 2) = lp1;
    if (hi2) {
        size_t o2f = (size_t)row * 1024 + tid * 4;
        *reinterpret_cast<__half2*>(hi2 + o2f)     = hp0;
        *reinterpret_cast<__half2*>(hi2 + o2f + 2) = hp1;
        *reinterpret_cast<__half2*>(lo2 + o2f)     = lp0;
        *reinterpret_cast<__half2*>(lo2 + o2f + 2) = lp1;
    }
}

// ---------------------------------------------------------------------------
// Weight transpose + hi/lo fp16 convert: W[K][Nd] -> T{h,l}[Nd][K]
// ---------------------------------------------------------------------------
__global__ void __launch_bounds__(256) convT(
    const float* __restrict__ W, __half* __restrict__ Th,
    __half* __restrict__ Tl, int Kdim, int Ndim)
{
    __shared__ float s[32][33];
    int n0 = blockIdx.x * 32, k0 = blockIdx.y * 32;
    int tx = threadIdx.x & 31, ty = threadIdx.x >> 5;
    #pragma unroll
    for (int i = 0; i < 4; i++) {
        int k = k0 + ty + i * 8;
        s[ty + i * 8][tx] = W[(size_t)k * Ndim + n0 + tx];
    }
    __syncthreads();
    #pragma unroll
    for (int i = 0; i < 4; i++) {
        int n = n0 + ty + i * 8;
        float v = s[tx][ty + i * 8];
        __half h = __float2half_rn(v);
        __half l = __float2half_rn(v - __half2float(h));
        Th[(size_t)n * Kdim + k0 + tx] = h;
        Tl[(size_t)n * Kdim + k0 + tx] = l;
    }
}

// ---------------------------------------------------------------------------
// mma.sync GEMM: C = A @ B^T, fp16 hi/lo, fp32 acc.
//   Block tile 128x128, BK=32, 8 warps (4m x 2n), warp tile 32x64.
//   3-stage cp.async pipeline, one __syncthreads per k-iter.
//   Pass count per block: col < split_col -> 2-pass (hh + hl, drops Al*B
//   which is ~2^-12 relative: fine for anything feeding softmax scores);
//   col >= split_col -> 3-pass (hh + hl + lh, error ~2^-24).
// ---------------------------------------------------------------------------
#define NKT   32
#define ROWB  80
#define MATB  (128 * ROWB)     // 10240 B per matrix tile
#define STGB  (4 * MATB)       // 40960 B per stage (Ah, Al, Bh, Bl)
#define GSMEM (3 * STGB)       // 122880 B

__global__ void __launch_bounds__(256) gemm_mma(
    const __half* __restrict__ Ah, const __half* __restrict__ Al,
    const __half* __restrict__ Bh, const __half* __restrict__ Bl,
    float* __restrict__ C, int ldc, int split_col)
{
    extern __shared__ char smem[];
    const int tid  = threadIdx.x;
    const int lane = tid & 31, wid = tid >> 5;
    const int wm = wid & 3, wn = wid >> 2;          // 4 x 2 warps

    const size_t arow0 = (size_t)blockIdx.y * 128;
    const size_t bcol0 = (size_t)blockIdx.x * 128;
    const bool use3 = ((int)bcol0 >= split_col);

    const __half* src0 = Ah + arow0 * 1024;
    const __half* src1 = Al + arow0 * 1024;
    const __half* src2 = Bh + bcol0 * 1024;
    const __half* src3 = Bl + bcol0 * 1024;

    const unsigned smbase = su32(smem);

    // loader mapping: thread -> 2 16B chunks per matrix (128 rows x 4 chunks)
    const int q0   = tid * 2;
    const int lrow = q0 >> 2;            // 0..127
    const int c0   = q0 & 3;             // 0 or 2
    const unsigned sof0 = (unsigned)(lrow * ROWB + c0 * 16);
    const unsigned sof1 = sof0 + 16;
    const size_t   gof0 = (size_t)lrow * 1024 + c0 * 8;

    // ldmatrix per-lane offsets
    const unsigned rbA = (unsigned)((wm * 32 + (lane & 15)) * ROWB);
    const unsigned hiA = (unsigned)(lane >> 4);
    const unsigned rbB = (unsigned)((wn * 64 + ((lane >> 4) << 3) + (lane & 7)) * ROWB);
    const unsigned hiB = (unsigned)((lane >> 3) & 1);

    float acc[2][8][4];
    #pragma unroll
    for (int i = 0; i < 2; i++)
        #pragma unroll
        for (int j = 0; j < 8; j++)
            #pragma unroll
            for (int k = 0; k < 4; k++) acc[i][j][k] = 0.f;

    auto load_stage = [&](int st, int kt) {
        unsigned sb = smbase + st * STGB;
        const __half* s;
        s = src0 + (size_t)kt * 32;
        CPA16(sb + sof0,            s + gof0);
        CPA16(sb + sof1,            s + gof0 + 8);
        if (use3) {
            s = src1 + (size_t)kt * 32;
            CPA16(sb + MATB + sof0, s + gof0);
            CPA16(sb + MATB + sof1, s + gof0 + 8);
        }
        s = src2 + (size_t)kt * 32;
        CPA16(sb + 2 * MATB + sof0, s + gof0);
        CPA16(sb + 2 * MATB + sof1, s + gof0 + 8);
        s = src3 + (size_t)kt * 32;
        CPA16(sb + 3 * MATB + sof0, s + gof0);
        CPA16(sb + 3 * MATB + sof1, s + gof0 + 8);
    };

    load_stage(0, 0);
    CPA_COMMIT();
    load_stage(1, 1);
    CPA_COMMIT();

    int sc = 0;   // stage index of current k-iter
    for (int kt = 0; kt < NKT; kt++) {
        if (kt + 2 < NKT) { CPA_WAIT1(); } else { CPA_WAIT0(); }
        __syncthreads();

        if (kt + 2 < NKT) {
            int sl = sc + 2; if (sl >= 3) sl -= 3;
            load_stage(sl, kt + 2);
            CPA_COMMIT();
        }

        unsigned base = smbase + sc * STGB;
        #pragma unroll
        for (int ks = 0; ks < 2; ks++) {
            unsigned ah[2][4], al[2][4], bh[4][4], bl[4][4];
            unsigned chA = (unsigned)((ks * 2 + hiA) << 4);
            unsigned chB = (unsigned)((ks * 2 + hiB) << 4);
            #pragma unroll
            for (int mi = 0; mi < 2; mi++) {
                unsigned ra = rbA + mi * (16 * ROWB);
                LDSM4(ah[mi], base + ra + chA);
                if (use3) LDSM4(al[mi], base + MATB + ra + chA);
            }
            #pragma unroll
            for (int nb = 0; nb < 4; nb++) {
                unsigned rb = rbB + nb * (16 * ROWB);
                LDSM4(bh[nb], base + 2 * MATB + rb + chB);
                LDSM4(bl[nb], base + 3 * MATB + rb + chB);
            }
            #pragma unroll
            for (int mi = 0; mi < 2; mi++)
                #pragma unroll
                for (int ni = 0; ni < 8; ni++) {
                    int nb = ni >> 1, pr = (ni & 1) * 2;
                    MMA16816(acc[mi][ni], ah[mi], bh[nb][pr], bh[nb][pr + 1]);  // hh
                    MMA16816(acc[mi][ni], ah[mi], bl[nb][pr], bl[nb][pr + 1]);  // hl
                    if (use3)
                        MMA16816(acc[mi][ni], al[mi], bh[nb][pr], bh[nb][pr + 1]);  // lh
                }
        }
        if (++sc == 3) sc = 0;
    }

    // epilogue
    const int lr  = lane >> 2;
    const int lc2 = (lane & 3) * 2;
    #pragma unroll
    for (int mi = 0; mi < 2; mi++) {
        size_t r0 = arow0 + wm * 32 + mi * 16 + lr;
        #pragma unroll
        for (int ni = 0; ni < 8; ni++) {
            size_t col = bcol0 + wn * 64 + ni * 8 + lc2;
            *reinterpret_cast<float2*>(C + r0 * ldc + col) =
                make_float2(acc[mi][ni][0], acc[mi][ni][1]);
            *reinterpret_cast<float2*>(C + (r0 + 8) * ldc + col) =
                make_float2(acc[mi][ni][2], acc[mi][ni][3]);
        }
    }
}

// ---------------------------------------------------------------------------
// Attention (split-KV, packed f32x2 FMAs). Block = (h, b, split); thread = n.
// p = exp(q.k) * mask  (rowmax and the +1 additive constant cancel in softmax)
// ---------------------------------------------------------------------------
__global__ void __launch_bounds__(256, 1) attn_kernel(
    const float* __restrict__ q, const float* __restrict__ kv,
    const int* __restrict__ mask, float* __restrict__ pacc,
    float* __restrict__ pl)
{
    int h = blockIdx.x, b = blockIdx.y, sp = blockIdx.z;
    int tid = threadIdx.x;

    __shared__ alignas(16) float k_s[64][64];
    __shared__ alignas(16) float v_s[64][64];
    __shared__ float m_s[64];

    unsigned long long qp[32], ap[32];
    const float* qrow = q + (size_t)(b * N_ + tid) * INNER_ + h * 64;
    #pragma unroll
    for (int d = 0; d < 16; d++) {
        float4 t = reinterpret_cast<const float4*>(qrow)[d];
        t.x *= 0.125f; t.y *= 0.125f; t.z *= 0.125f; t.w *= 0.125f;
        asm("mov.b64 %0, {%1, %2};" : "=l"(qp[2 * d])     : "f"(t.x), "f"(t.y));
        asm("mov.b64 %0, {%1, %2};" : "=l"(qp[2 * d + 1]) : "f"(t.z), "f"(t.w));
    }
    #pragma unroll
    for (int i = 0; i < 32; i++) ap[i] = 0ull;
    float l = 0.f;

    const size_t kvbase = (size_t)b * J_ * 2048 + (size_t)h * 64;

    for (int j0 = sp * JSPLIT; j0 < (sp + 1) * JSPLIT; j0 += 64) {
        #pragma unroll
        for (int t = 0; t < 4; t++) {
            int idx = tid + t * 256;
            int r = idx >> 4, c = (idx & 15) << 2;
            size_t g = kvbase + (size_t)(j0 + r) * 2048 + c;
            *reinterpret_cast<float4*>(&k_s[r][c]) = *reinterpret_cast<const float4*>(kv + g);
            *reinterpret_cast<float4*>(&v_s[r][c]) = *reinterpret_cast<const float4*>(kv + g + 1024);
        }
        if (tid < 64) {
            int j = j0 + tid;
            m_s[tid] = (j < M_) ? (mask[b * M_ + j] ? 0.f : 1.f) : 1.f;
        }
        __syncthreads();

        #pragma unroll 1
        for (int jj = 0; jj < 64; jj++) {
            const ulonglong2* kr = reinterpret_cast<const ulonglong2*>(&k_s[jj][0]);
            unsigned long long a0 = 0ull, a1 = 0ull, a2 = 0ull, a3 = 0ull;
            #pragma unroll
            for (int i = 0; i < 16; i += 2) {
                ulonglong2 kA = kr[i], kB = kr[i + 1];
                FMA2(a0, qp[2 * i],     kA.x, a0);
                FMA2(a1, qp[2 * i + 1], kA.y, a1);
                FMA2(a2, qp[2 * i + 2], kB.x, a2);
                FMA2(a3, qp[2 * i + 3], kB.y, a3);
            }
            float f0, f1, f2, f3, f4, f5, f6, f7;
            asm("mov.b64 {%0,%1}, %2;" : "=f"(f0), "=f"(f1) : "l"(a0));
            asm("mov.b64 {%0,%1}, %2;" : "=f"(f2), "=f"(f3) : "l"(a1));
            asm("mov.b64 {%0,%1}, %2;" : "=f"(f4), "=f"(f5) : "l"(a2));
            asm("mov.b64 {%0,%1}, %2;" : "=f"(f6), "=f"(f7) : "l"(a3));
            float p = __expf(((f0 + f1) + (f2 + f3)) + ((f4 + f5) + (f6 + f7))) * m_s[jj];
            l += p;
            unsigned long long pp;
            asm("mov.b64 %0, {%1, %1};" : "=l"(pp) : "f"(p));
            const ulonglong2* vr = reinterpret_cast<const ulonglong2*>(&v_s[jj][0]);
            #pragma unroll
            for (int i = 0; i < 16; i++) {
                ulonglong2 vv = vr[i];
                FMA2(ap[2 * i],     pp, vv.x, ap[2 * i]);
                FMA2(ap[2 * i + 1], pp, vv.y, ap[2 * i + 1]);
            }
        }
        __syncthreads();
    }

    unsigned long long* op = reinterpret_cast<unsigned long long*>(
        pacc + ((size_t)((sp * B_ + b) * N_ + tid)) * INNER_ + h * 64);
    #pragma unroll
    for (int i = 0; i < 32; i++) op[i] = ap[i];
    pl[((size_t)(sp * B_ + b) * N_ + tid) * H_ + h] = l;
}

// ---------------------------------------------------------------------------
// Merge split-KV partials -> fp16 hi/lo for the Wo GEMM. grid=2048 rows.
// ---------------------------------------------------------------------------
__global__ void __launch_bounds__(256) merge_kernel(
    const float* __restrict__ pacc, const float* __restrict__ pl,
    __half* __restrict__ oh, __half* __restrict__ ol)
{
    int row = blockIdx.x;
    int tid = threadIdx.x;
    int col = tid * 4;
    int h = col >> 6;

    float lsum = 0.f;
    #pragma unroll
    for (int sp = 0; sp < SPLITS; sp++)
        lsum += pl[((size_t)(sp * (B_ * N_) + row)) * H_ + h];

    float4 a = make_float4(0.f, 0.f, 0.f, 0.f);
    #pragma unroll
    for (int sp = 0; sp < SPLITS; sp++) {
        float4 t = *reinterpret_cast<const float4*>(
            pacc + ((size_t)(sp * (B_ * N_) + row)) * 1024 + col);
        a.x += t.x; a.y += t.y; a.z += t.z; a.w += t.w;
    }
    float inv = 1.f / lsum;
    a.x *= inv; a.y *= inv; a.z *= inv; a.w *= inv;

    __half h0 = __float2half_rn(a.x);
    __half h1 = __float2half_rn(a.y);
    __half h2 = __float2half_rn(a.z);
    __half h3 = __float2half_rn(a.w);
    __half l0 = __float2half_rn(a.x - __half2float(h0));
    __half l1 = __float2half_rn(a.y - __half2float(h1));
    __half l2 = __float2half_rn(a.z - __half2float(h2));
    __half l3 = __float2half_rn(a.w - __half2float(h3));

    size_t off = (size_t)row * 1024 + col;
    *reinterpret_cast<__half2*>(oh + off)     = __halves2half2(h0, h1);
    *reinterpret_cast<__half2*>(oh + off + 2) = __halves2half2(h2, h3);
    *reinterpret_cast<__half2*>(ol + off)     = __halves2half2(l0, l1);
    *reinterpret_cast<__half2*>(ol + off + 2) = __halves2half2(l2, l3);
}

// ---------------------------------------------------------------------------
extern "C" void kernel_launch(void* const* d_in, const int* in_sizes, int n_in,
                              void* d_out, int out_size)
{
    const float* x       = (const float*)d_in[0];
    const float* latents = (const float*)d_in[1];
    const int*   xmask   = (const int*)  d_in[2];
    const float* nm_g    = (const float*)d_in[3];
    const float* nm_b    = (const float*)d_in[4];
    const float* nl_g    = (const float*)d_in[5];
    const float* nl_b    = (const float*)d_in[6];
    const float* Wq      = (const float*)d_in[7];
    const float* Wkv     = (const float*)d_in[8];
    const float* Wo      = (const float*)d_in[9];
    float*       out     = (float*)d_out;

    __half *ah, *al, *lath, *latl, *atth, *attl;
    __half *wkvh, *wkvl, *wqh, *wql, *woh, *wol;
    float *kvb, *qb, *pacc, *pl;
    cudaGetSymbolAddress((void**)&ah,   g_ah);
    cudaGetSymbolAddress((void**)&al,   g_al);
    cudaGetSymbolAddress((void**)&lath, g_lath);
    cudaGetSymbolAddress((void**)&latl, g_latl);
    cudaGetSymbolAddress((void**)&kvb,  g_kv);
    cudaGetSymbolAddress((void**)&qb,   g_q);
    cudaGetSymbolAddress((void**)&atth, g_atth);
    cudaGetSymbolAddress((void**)&attl, g_attl);
    cudaGetSymbolAddress((void**)&wkvh, g_wkvh);
    cudaGetSymbolAddress((void**)&wkvl, g_wkvl);
    cudaGetSymbolAddress((void**)&wqh,  g_wqh);
    cudaGetSymbolAddress((void**)&wql,  g_wql);
    cudaGetSymbolAddress((void**)&woh,  g_woh);
    cudaGetSymbolAddress((void**)&wol,  g_wol);
    cudaGetSymbolAddress((void**)&pacc, g_pacc);
    cudaGetSymbolAddress((void**)&pl,   g_pl);

    cudaFuncSetAttribute(gemm_mma, cudaFuncAttributeMaxDynamicSharedMemorySize, GSMEM);

    // Order chosen so the fixed ncu window (-s 5 -c 1) likely lands on gemm_kv.
    convT<<<dim3(2048 / 32, 1024 / 32), 256>>>(Wkv, wkvh, wkvl, 1024, 2048);
    ln_kernel<<<B_ * M_, 256>>>(x,       nm_g, nm_b, ah, al, M_, 0,  nullptr, nullptr);
    ln_kernel<<<B_ * N_, 256>>>(latents, nl_g, nl_b, ah, al, N_, M_, lath,    latl);

    // kv = kvin @ Wkv : cols [0,1024) = K (2-pass), cols [1024,2048) = V (3-pass)
    gemm_mma<<<dim3(2048 / 128, (B_ * J_) / 128), 256, GSMEM>>>(
        ah, al, wkvh, wkvl, kvb, 2048, 1024);

    // q = ln(latents) @ Wq : all 2-pass (feeds scores only)
    convT<<<dim3(1024 / 32, 1024 / 32), 256>>>(Wq, wqh, wql, 1024, 1024);
    gemm_mma<<<dim3(1024 / 128, (B_ * N_) / 128), 256, GSMEM>>>(
        lath, latl, wqh, wql, qb, 1024, 1 << 30);

    // attention (split-KV) + merge
    attn_kernel<<<dim3(H_, B_, SPLITS), 256>>>(qb, kvb, xmask, pacc, pl);
    merge_kernel<<<B_ * N_, 256>>>(pacc, pl, atth, attl);

    // out = att @ Wo : 3-pass everywhere (direct output path)
    convT<<<dim3(1024 / 32, 1024 / 32), 256>>>(Wo, woh, wol, 1024, 1024);
    gemm_mma<<<dim3(1024 / 128, (B_ * N_) / 128), 256, GSMEM>>>(
        atth, attl, woh, wol, out, 1024, 0);
}

// round 13
// speedup vs baseline: 1.0003x; 1.0003x over previous
#include <cuda_runtime.h>
#include <cuda_fp16.h>
#include <cstdint>

// ---------------------------------------------------------------------------
// PerceiverAttention — mma.sync fp16 hi/lo GEMMs (mixed 2/3-pass)
//                      + f32x2 split-KV attention
//   B=8, M=4096, N=256, DIM=1024, HEADS=16, DH=64, J=4352, INNER=1024
// ---------------------------------------------------------------------------

#define B_     8
#define M_     4096
#define N_     256
#define D_     1024
#define H_     16
#define J_     (M_ + N_)      // 4352
#define INNER_ 1024
#define SPLITS 4
#define JSPLIT (J_ / SPLITS)  // 1088

// ---------------- static device scratch -------------------------------------
__device__ __half g_ah  [(size_t)B_ * J_ * D_];
__device__ __half g_al  [(size_t)B_ * J_ * D_];
__device__ __half g_lath[(size_t)B_ * N_ * D_];
__device__ __half g_latl[(size_t)B_ * N_ * D_];
__device__ float  g_kv  [(size_t)B_ * J_ * 2 * INNER_];
__device__ float  g_q   [(size_t)B_ * N_ * INNER_];
__device__ __half g_atth[(size_t)B_ * N_ * INNER_];
__device__ __half g_attl[(size_t)B_ * N_ * INNER_];
__device__ __half g_wkvh[(size_t)2 * INNER_ * D_];
__device__ __half g_wkvl[(size_t)2 * INNER_ * D_];
__device__ __half g_wqh [(size_t)INNER_ * D_];
__device__ __half g_wql [(size_t)INNER_ * D_];
__device__ __half g_woh [(size_t)INNER_ * D_];
__device__ __half g_wol [(size_t)INNER_ * D_];
__device__ float  g_pacc[(size_t)SPLITS * B_ * N_ * INNER_];
__device__ float  g_pl  [(size_t)SPLITS * B_ * N_ * H_];

// ---------------- PTX helpers (plain sm_103-legal) ---------------------------
__device__ __forceinline__ unsigned su32(const void* p) {
    unsigned a;
    asm("{ .reg .u64 t; cvta.to.shared.u64 t, %1; cvt.u32.u64 %0, t; }"
        : "=r"(a) : "l"(p));
    return a;
}

#define CPA16(saddr, gptr) \
    asm volatile("cp.async.cg.shared.global [%0], [%1], 16;" \
                 :: "r"(saddr), "l"(gptr))
#define CPA_COMMIT() asm volatile("cp.async.commit_group;" ::: "memory")
#define CPA_WAIT1()  asm volatile("cp.async.wait_group 1;" ::: "memory")
#define CPA_WAIT0()  asm volatile("cp.async.wait_group 0;" ::: "memory")

#define LDSM4(r, addr) \
    asm volatile("ldmatrix.sync.aligned.m8n8.x4.shared.b16 {%0,%1,%2,%3}, [%4];" \
        : "=r"((r)[0]), "=r"((r)[1]), "=r"((r)[2]), "=r"((r)[3]) : "r"(addr))

#define MMA16816(c, a, b0, b1) \
    asm volatile("mma.sync.aligned.m16n8k16.row.col.f32.f16.f16.f32 " \
        "{%0,%1,%2,%3}, {%4,%5,%6,%7}, {%8,%9}, {%0,%1,%2,%3};" \
        : "+f"((c)[0]), "+f"((c)[1]), "+f"((c)[2]), "+f"((c)[3]) \
        : "r"((a)[0]), "r"((a)[1]), "r"((a)[2]), "r"((a)[3]), "r"(b0), "r"(b1))

// f32x2 packed fma (sm_103a)
#define FMA2(d, a, b, c) \
    asm("fma.rn.f32x2 %0, %1, %2, %3;" : "=l"(d) : "l"(a), "l"(b), "l"(c))

// ---------------------------------------------------------------------------
// LayerNorm -> fp16 hi/lo (kvin layout + optional compact latent copy)
// ---------------------------------------------------------------------------
__global__ void __launch_bounds__(256) ln_kernel(
    const float* __restrict__ x, const float* __restrict__ g,
    const float* __restrict__ be,
    __half* __restrict__ hi, __half* __restrict__ lo,
    int rpb, int base,
    __half* __restrict__ hi2, __half* __restrict__ lo2)
{
    int row = blockIdx.x;
    int tid = threadIdx.x;

    const float4* xr = reinterpret_cast<const float4*>(x) + (size_t)row * 256;
    float4 v = xr[tid];
    float s  = v.x + v.y + v.z + v.w;
    float ss = v.x * v.x + v.y * v.y + v.z * v.z + v.w * v.w;
    #pragma unroll
    for (int o = 16; o > 0; o >>= 1) {
        s  += __shfl_xor_sync(0xffffffffu, s,  o);
        ss += __shfl_xor_sync(0xffffffffu, ss, o);
    }
    __shared__ float ssum[8], ssq[8], sstat[2];
    int wid = tid >> 5, lid = tid & 31;
    if (lid == 0) { ssum[wid] = s; ssq[wid] = ss; }
    __syncthreads();
    if (tid == 0) {
        float a = 0.f, q2 = 0.f;
        #pragma unroll
        for (int i = 0; i < 8; i++) { a += ssum[i]; q2 += ssq[i]; }
        float mu  = a * (1.0f / 1024.0f);
        float var = q2 * (1.0f / 1024.0f) - mu * mu;
        sstat[0] = mu;
        sstat[1] = rsqrtf(var + 1e-5f);
    }
    __syncthreads();
    float mu = sstat[0], rs = sstat[1];

    float4 gv = reinterpret_cast<const float4*>(g)[tid];
    float4 bv = reinterpret_cast<const float4*>(be)[tid];
    float o0 = (v.x - mu) * rs * gv.x + bv.x;
    float o1 = (v.y - mu) * rs * gv.y + bv.y;
    float o2 = (v.z - mu) * rs * gv.z + bv.z;
    float o3 = (v.w - mu) * rs * gv.w + bv.w;

    __half h0 = __float2half_rn(o0);
    __half h1 = __float2half_rn(o1);
    __half h2 = __float2half_rn(o2);
    __half h3 = __float2half_rn(o3);
    __half l0 = __float2half_rn(o0 - __half2float(h0));
    __half l1 = __float2half_rn(o1 - __half2float(h1));
    __half l2 = __float2half_rn(o2 - __half2float(h2));
    __half l3 = __float2half_rn(o3 - __half2float(h3));
    __half2 hp0 = __halves2half2(h0, h1), hp1 = __halves2half2(h2, h3);
    __half2 lp0 = __halves2half2(l0, l1), lp1 = __halves2half2(l2, l3);

    int b = row / rpb;
    int r = row - b * rpb;
    size_t off = ((size_t)b * J_ + base + r) * 1024 + tid * 4;
    *reinterpret_cast<__half2*>(hi + off)     = hp0;
    *reinterpret_cast<__half2*>(hi + off + 2) = hp1;
    *reinterpret_cast<__half2*>(lo + off)     = lp0;
    *reinterpret_cast<__half2*>(lo + off + 2) = lp1;
    if (hi2) {
        size_t o2f = (size_t)row * 1024 + tid * 4;
        *reinterpret_cast<__half2*>(hi2 + o2f)     = hp0;
        *reinterpret_cast<__half2*>(hi2 + o2f + 2) = hp1;
        *reinterpret_cast<__half2*>(lo2 + o2f)     = lp0;
        *reinterpret_cast<__half2*>(lo2 + o2f + 2) = lp1;
    }
}

// ---------------------------------------------------------------------------
// Weight transpose + hi/lo fp16 convert: W[K][Nd] -> T{h,l}[Nd][K]
// ---------------------------------------------------------------------------
__global__ void __launch_bounds__(256) convT(
    const float* __restrict__ W, __half* __restrict__ Th,
    __half* __restrict__ Tl, int Kdim, int Ndim)
{
    __shared__ float s[32][33];
    int n0 = blockIdx.x * 32, k0 = blockIdx.y * 32;
    int tx = threadIdx.x & 31, ty = threadIdx.x >> 5;
    #pragma unroll
    for (int i = 0; i < 4; i++) {
        int k = k0 + ty + i * 8;
        s[ty + i * 8][tx] = W[(size_t)k * Ndim + n0 + tx];
    }
    __syncthreads();
    #pragma unroll
    for (int i = 0; i < 4; i++) {
        int n = n0 + ty + i * 8;
        float v = s[tx][ty + i * 8];
        __half h = __float2half_rn(v);
        __half l = __float2half_rn(v - __half2float(h));
        Th[(size_t)n * Kdim + k0 + tx] = h;
        Tl[(size_t)n * Kdim + k0 + tx] = l;
    }
}

// ---------------------------------------------------------------------------
// mma.sync GEMM: C = A @ B^T, fp16 hi/lo, fp32 acc.
//   Block tile 128x128, BK=32, 8 warps (4m x 2n), warp tile 32x64.
//   3-stage cp.async pipeline, one __syncthreads per k-iter.
//   Pass count per block: col < split_col -> 2-pass (hh + hl, drops Al*B
//   which is ~2^-12 relative: fine for anything feeding softmax scores);
//   col >= split_col -> 3-pass (hh + hl + lh, error ~2^-24).
// ---------------------------------------------------------------------------
#define NKT   32
#define ROWB  80
#define MATB  (128 * ROWB)     // 10240 B per matrix tile
#define STGB  (4 * MATB)       // 40960 B per stage (Ah, Al, Bh, Bl)
#define GSMEM (3 * STGB)       // 122880 B

__global__ void __launch_bounds__(256) gemm_mma(
    const __half* __restrict__ Ah, const __half* __restrict__ Al,
    const __half* __restrict__ Bh, const __half* __restrict__ Bl,
    float* __restrict__ C, int ldc, int split_col)
{
    extern __shared__ char smem[];
    const int tid  = threadIdx.x;
    const int lane = tid & 31, wid = tid >> 5;
    const int wm = wid & 3, wn = wid >> 2;          // 4 x 2 warps

    const size_t arow0 = (size_t)blockIdx.y * 128;
    const size_t bcol0 = (size_t)blockIdx.x * 128;
    const bool use3 = ((int)bcol0 >= split_col);

    const __half* src0 = Ah + arow0 * 1024;
    const __half* src1 = Al + arow0 * 1024;
    const __half* src2 = Bh + bcol0 * 1024;
    const __half* src3 = Bl + bcol0 * 1024;

    const unsigned smbase = su32(smem);

    // loader mapping: thread -> 2 16B chunks per matrix (128 rows x 4 chunks)
    const int q0   = tid * 2;
    const int lrow = q0 >> 2;            // 0..127
    const int c0   = q0 & 3;             // 0 or 2
    const unsigned sof0 = (unsigned)(lrow * ROWB + c0 * 16);
    const unsigned sof1 = sof0 + 16;
    const size_t   gof0 = (size_t)lrow * 1024 + c0 * 8;

    // ldmatrix per-lane offsets
    const unsigned rbA = (unsigned)((wm * 32 + (lane & 15)) * ROWB);
    const unsigned hiA = (unsigned)(lane >> 4);
    const unsigned rbB = (unsigned)((wn * 64 + ((lane >> 4) << 3) + (lane & 7)) * ROWB);
    const unsigned hiB = (unsigned)((lane >> 3) & 1);

    float acc[2][8][4];
    #pragma unroll
    for (int i = 0; i < 2; i++)
        #pragma unroll
        for (int j = 0; j < 8; j++)
            #pragma unroll
            for (int k = 0; k < 4; k++) acc[i][j][k] = 0.f;

    auto load_stage = [&](int st, int kt) {
        unsigned sb = smbase + st * STGB;
        const __half* s;
        s = src0 + (size_t)kt * 32;
        CPA16(sb + sof0,            s + gof0);
        CPA16(sb + sof1,            s + gof0 + 8);
        if (use3) {
            s = src1 + (size_t)kt * 32;
            CPA16(sb + MATB + sof0, s + gof0);
            CPA16(sb + MATB + sof1, s + gof0 + 8);
        }
        s = src2 + (size_t)kt * 32;
        CPA16(sb + 2 * MATB + sof0, s + gof0);
        CPA16(sb + 2 * MATB + sof1, s + gof0 + 8);
        s = src3 + (size_t)kt * 32;
        CPA16(sb + 3 * MATB + sof0, s + gof0);
        CPA16(sb + 3 * MATB + sof1, s + gof0 + 8);
    };

    load_stage(0, 0);
    CPA_COMMIT();
    load_stage(1, 1);
    CPA_COMMIT();

    int sc = 0;   // stage index of current k-iter
    for (int kt = 0; kt < NKT; kt++) {
        if (kt + 2 < NKT) { CPA_WAIT1(); } else { CPA_WAIT0(); }
        __syncthreads();

        if (kt + 2 < NKT) {
            int sl = sc + 2; if (sl >= 3) sl -= 3;
            load_stage(sl, kt + 2);
            CPA_COMMIT();
        }

        unsigned base = smbase + sc * STGB;
        #pragma unroll
        for (int ks = 0; ks < 2; ks++) {
            unsigned ah[2][4], al[2][4], bh[4][4], bl[4][4];
            unsigned chA = (unsigned)((ks * 2 + hiA) << 4);
            unsigned chB = (unsigned)((ks * 2 + hiB) << 4);
            #pragma unroll
            for (int mi = 0; mi < 2; mi++) {
                unsigned ra = rbA + mi * (16 * ROWB);
                LDSM4(ah[mi], base + ra + chA);
                if (use3) LDSM4(al[mi], base + MATB + ra + chA);
            }
            #pragma unroll
            for (int nb = 0; nb < 4; nb++) {
                unsigned rb = rbB + nb * (16 * ROWB);
                LDSM4(bh[nb], base + 2 * MATB + rb + chB);
                LDSM4(bl[nb], base + 3 * MATB + rb + chB);
            }
            #pragma unroll
            for (int mi = 0; mi < 2; mi++)
                #pragma unroll
                for (int ni = 0; ni < 8; ni++) {
                    int nb = ni >> 1, pr = (ni & 1) * 2;
                    MMA16816(acc[mi][ni], ah[mi], bh[nb][pr], bh[nb][pr + 1]);  // hh
                    MMA16816(acc[mi][ni], ah[mi], bl[nb][pr], bl[nb][pr + 1]);  // hl
                    if (use3)
                        MMA16816(acc[mi][ni], al[mi], bh[nb][pr], bh[nb][pr + 1]);  // lh
                }
        }
        if (++sc == 3) sc = 0;
    }

    // epilogue
    const int lr  = lane >> 2;
    const int lc2 = (lane & 3) * 2;
    #pragma unroll
    for (int mi = 0; mi < 2; mi++) {
        size_t r0 = arow0 + wm * 32 + mi * 16 + lr;
        #pragma unroll
        for (int ni = 0; ni < 8; ni++) {
            size_t col = bcol0 + wn * 64 + ni * 8 + lc2;
            *reinterpret_cast<float2*>(C + r0 * ldc + col) =
                make_float2(acc[mi][ni][0], acc[mi][ni][1]);
            *reinterpret_cast<float2*>(C + (r0 + 8) * ldc + col) =
                make_float2(acc[mi][ni][2], acc[mi][ni][3]);
        }
    }
}

// ---------------------------------------------------------------------------
// Attention (split-KV, packed f32x2 FMAs). Block = (h, b, split); thread = n.
// p = exp(q.k) * mask  (rowmax and the +1 additive constant cancel in softmax)
// ---------------------------------------------------------------------------
__global__ void __launch_bounds__(256, 1) attn_kernel(
    const float* __restrict__ q, const float* __restrict__ kv,
    const int* __restrict__ mask, float* __restrict__ pacc,
    float* __restrict__ pl)
{
    int h = blockIdx.x, b = blockIdx.y, sp = blockIdx.z;
    int tid = threadIdx.x;

    __shared__ alignas(16) float k_s[64][64];
    __shared__ alignas(16) float v_s[64][64];
    __shared__ float m_s[64];

    unsigned long long qp[32], ap[32];
    const float* qrow = q + (size_t)(b * N_ + tid) * INNER_ + h * 64;
    #pragma unroll
    for (int d = 0; d < 16; d++) {
        float4 t = reinterpret_cast<const float4*>(qrow)[d];
        t.x *= 0.125f; t.y *= 0.125f; t.z *= 0.125f; t.w *= 0.125f;
        asm("mov.b64 %0, {%1, %2};" : "=l"(qp[2 * d])     : "f"(t.x), "f"(t.y));
        asm("mov.b64 %0, {%1, %2};" : "=l"(qp[2 * d + 1]) : "f"(t.z), "f"(t.w));
    }
    #pragma unroll
    for (int i = 0; i < 32; i++) ap[i] = 0ull;
    float l = 0.f;

    const size_t kvbase = (size_t)b * J_ * 2048 + (size_t)h * 64;

    for (int j0 = sp * JSPLIT; j0 < (sp + 1) * JSPLIT; j0 += 64) {
        #pragma unroll
        for (int t = 0; t < 4; t++) {
            int idx = tid + t * 256;
            int r = idx >> 4, c = (idx & 15) << 2;
            size_t g = kvbase + (size_t)(j0 + r) * 2048 + c;
            *reinterpret_cast<float4*>(&k_s[r][c]) = *reinterpret_cast<const float4*>(kv + g);
            *reinterpret_cast<float4*>(&v_s[r][c]) = *reinterpret_cast<const float4*>(kv + g + 1024);
        }
        if (tid < 64) {
            int j = j0 + tid;
            m_s[tid] = (j < M_) ? (mask[b * M_ + j] ? 0.f : 1.f) : 1.f;
        }
        __syncthreads();

        #pragma unroll 1
        for (int jj = 0; jj < 64; jj++) {
            const ulonglong2* kr = reinterpret_cast<const ulonglong2*>(&k_s[jj][0]);
            unsigned long long a0 = 0ull, a1 = 0ull, a2 = 0ull, a3 = 0ull;
            #pragma unroll
            for (int i = 0; i < 16; i += 2) {
                ulonglong2 kA = kr[i], kB = kr[i + 1];
                FMA2(a0, qp[2 * i],     kA.x, a0);
                FMA2(a1, qp[2 * i + 1], kA.y, a1);
                FMA2(a2, qp[2 * i + 2], kB.x, a2);
                FMA2(a3, qp[2 * i + 3], kB.y, a3);
            }
            float f0, f1, f2, f3, f4, f5, f6, f7;
            asm("mov.b64 {%0,%1}, %2;" : "=f"(f0), "=f"(f1) : "l"(a0));
            asm("mov.b64 {%0,%1}, %2;" : "=f"(f2), "=f"(f3) : "l"(a1));
            asm("mov.b64 {%0,%1}, %2;" : "=f"(f4), "=f"(f5) : "l"(a2));
            asm("mov.b64 {%0,%1}, %2;" : "=f"(f6), "=f"(f7) : "l"(a3));
            float p = __expf(((f0 + f1) + (f2 + f3)) + ((f4 + f5) + (f6 + f7))) * m_s[jj];
            l += p;
            unsigned long long pp;
            asm("mov.b64 %0, {%1, %1};" : "=l"(pp) : "f"(p));
            const ulonglong2* vr = reinterpret_cast<const ulonglong2*>(&v_s[jj][0]);
            #pragma unroll
            for (int i = 0; i < 16; i++) {
                ulonglong2 vv = vr[i];
                FMA2(ap[2 * i],     pp, vv.x, ap[2 * i]);
                FMA2(ap[2 * i + 1], pp, vv.y, ap[2 * i + 1]);
            }
        }
        __syncthreads();
    }

    unsigned long long* op = reinterpret_cast<unsigned long long*>(
        pacc + ((size_t)((sp * B_ + b) * N_ + tid)) * INNER_ + h * 64);
    #pragma unroll
    for (int i = 0; i < 32; i++) op[i] = ap[i];
    pl[((size_t)(sp * B_ + b) * N_ + tid) * H_ + h] = l;
}

// ---------------------------------------------------------------------------
// Merge split-KV partials -> fp16 hi/lo for the Wo GEMM. grid=2048 rows.
// ---------------------------------------------------------------------------
__global__ void __launch_bounds__(256) merge_kernel(
    const float* __restrict__ pacc, const float* __restrict__ pl,
    __half* __restrict__ oh, __half* __restrict__ ol)
{
    int row = blockIdx.x;
    int tid = threadIdx.x;
    int col = tid * 4;
    int h = col >> 6;

    float lsum = 0.f;
    #pragma unroll
    for (int sp = 0; sp < SPLITS; sp++)
        lsum += pl[((size_t)(sp * (B_ * N_) + row)) * H_ + h];

    float4 a = make_float4(0.f, 0.f, 0.f, 0.f);
    #pragma unroll
    for (int sp = 0; sp < SPLITS; sp++) {
        float4 t = *reinterpret_cast<const float4*>(
            pacc + ((size_t)(sp * (B_ * N_) + row)) * 1024 + col);
        a.x += t.x; a.y += t.y; a.z += t.z; a.w += t.w;
    }
    float inv = 1.f / lsum;
    a.x *= inv; a.y *= inv; a.z *= inv; a.w *= inv;

    __half h0 = __float2half_rn(a.x);
    __half h1 = __float2half_rn(a.y);
    __half h2 = __float2half_rn(a.z);
    __half h3 = __float2half_rn(a.w);
    __half l0 = __float2half_rn(a.x - __half2float(h0));
    __half l1 = __float2half_rn(a.y - __half2float(h1));
    __half l2 = __float2half_rn(a.z - __half2float(h2));
    __half l3 = __float2half_rn(a.w - __half2float(h3));

    size_t off = (size_t)row * 1024 + col;
    *reinterpret_cast<__half2*>(oh + off)     = __halves2half2(h0, h1);
    *reinterpret_cast<__half2*>(oh + off + 2) = __halves2half2(h2, h3);
    *reinterpret_cast<__half2*>(ol + off)     = __halves2half2(l0, l1);
    *reinterpret_cast<__half2*>(ol + off + 2) = __halves2half2(l2, l3);
}

// ---------------------------------------------------------------------------
extern "C" void kernel_launch(void* const* d_in, const int* in_sizes, int n_in,
                              void* d_out, int out_size)
{
    const float* x       = (const float*)d_in[0];
    const float* latents = (const float*)d_in[1];
    const int*   xmask   = (const int*)  d_in[2];
    const float* nm_g    = (const float*)d_in[3];
    const float* nm_b    = (const float*)d_in[4];
    const float* nl_g    = (const float*)d_in[5];
    const float* nl_b    = (const float*)d_in[6];
    const float* Wq      = (const float*)d_in[7];
    const float* Wkv     = (const float*)d_in[8];
    const float* Wo      = (const float*)d_in[9];
    float*       out     = (float*)d_out;

    __half *ah, *al, *lath, *latl, *atth, *attl;
    __half *wkvh, *wkvl, *wqh, *wql, *woh, *wol;
    float *kvb, *qb, *pacc, *pl;
    cudaGetSymbolAddress((void**)&ah,   g_ah);
    cudaGetSymbolAddress((void**)&al,   g_al);
    cudaGetSymbolAddress((void**)&lath, g_lath);
    cudaGetSymbolAddress((void**)&latl, g_latl);
    cudaGetSymbolAddress((void**)&kvb,  g_kv);
    cudaGetSymbolAddress((void**)&qb,   g_q);
    cudaGetSymbolAddress((void**)&atth, g_atth);
    cudaGetSymbolAddress((void**)&attl, g_attl);
    cudaGetSymbolAddress((void**)&wkvh, g_wkvh);
    cudaGetSymbolAddress((void**)&wkvl, g_wkvl);
    cudaGetSymbolAddress((void**)&wqh,  g_wqh);
    cudaGetSymbolAddress((void**)&wql,  g_wql);
    cudaGetSymbolAddress((void**)&woh,  g_woh);
    cudaGetSymbolAddress((void**)&wol,  g_wol);
    cudaGetSymbolAddress((void**)&pacc, g_pacc);
    cudaGetSymbolAddress((void**)&pl,   g_pl);

    cudaFuncSetAttribute(gemm_mma, cudaFuncAttributeMaxDynamicSharedMemorySize, GSMEM);

    // Order chosen so the fixed ncu window (-s 5 -c 1) likely lands on gemm_kv.
    convT<<<dim3(2048 / 32, 1024 / 32), 256>>>(Wkv, wkvh, wkvl, 1024, 2048);
    ln_kernel<<<B_ * M_, 256>>>(x,       nm_g, nm_b, ah, al, M_, 0,  nullptr, nullptr);
    ln_kernel<<<B_ * N_, 256>>>(latents, nl_g, nl_b, ah, al, N_, M_, lath,    latl);

    // kv = kvin @ Wkv : cols [0,1024) = K (2-pass), cols [1024,2048) = V (3-pass)
    gemm_mma<<<dim3(2048 / 128, (B_ * J_) / 128), 256, GSMEM>>>(
        ah, al, wkvh, wkvl, kvb, 2048, 1024);

    // q = ln(latents) @ Wq : all 2-pass (feeds scores only)
    convT<<<dim3(1024 / 32, 1024 / 32), 256>>>(Wq, wqh, wql, 1024, 1024);
    gemm_mma<<<dim3(1024 / 128, (B_ * N_) / 128), 256, GSMEM>>>(
        lath, latl, wqh, wql, qb, 1024, 1 << 30);

    // attention (split-KV) + merge
    attn_kernel<<<dim3(H_, B_, SPLITS), 256>>>(qb, kvb, xmask, pacc, pl);
    merge_kernel<<<B_ * N_, 256>>>(pacc, pl, atth, attl);

    // out = att @ Wo : 3-pass everywhere (direct output path)
    convT<<<dim3(1024 / 32, 1024 / 32), 256>>>(Wo, woh, wol, 1024, 1024);
    gemm_mma<<<dim3(1024 / 128, (B_ * N_) / 128), 256, GSMEM>>>(
        atth, attl, woh, wol, out, 1024, 0);
}

// round 14
// speedup vs baseline: 1.0887x; 1.0883x over previous
#include <cuda_runtime.h>
#include <cuda_fp16.h>
#include <cstdint>

// ---------------------------------------------------------------------------
// PerceiverAttention — mma.sync fp16 hi/lo GEMMs (mixed 2/3-pass),
//   2-stage cp.async pipeline sized for 2 CTAs/SM, + f32x2 split-KV attention
//   B=8, M=4096, N=256, DIM=1024, HEADS=16, DH=64, J=4352, INNER=1024
// ---------------------------------------------------------------------------

#define B_     8
#define M_     4096
#define N_     256
#define D_     1024
#define H_     16
#define J_     (M_ + N_)      // 4352
#define INNER_ 1024
#define SPLITS 4
#define JSPLIT (J_ / SPLITS)  // 1088

// ---------------- static device scratch -------------------------------------
__device__ __half g_ah  [(size_t)B_ * J_ * D_];
__device__ __half g_al  [(size_t)B_ * J_ * D_];
__device__ __half g_lath[(size_t)B_ * N_ * D_];
__device__ __half g_latl[(size_t)B_ * N_ * D_];
__device__ float  g_kv  [(size_t)B_ * J_ * 2 * INNER_];
__device__ float  g_q   [(size_t)B_ * N_ * INNER_];
__device__ __half g_atth[(size_t)B_ * N_ * INNER_];
__device__ __half g_attl[(size_t)B_ * N_ * INNER_];
__device__ __half g_wkvh[(size_t)2 * INNER_ * D_];
__device__ __half g_wkvl[(size_t)2 * INNER_ * D_];
__device__ __half g_wqh [(size_t)INNER_ * D_];
__device__ __half g_wql [(size_t)INNER_ * D_];
__device__ __half g_woh [(size_t)INNER_ * D_];
__device__ __half g_wol [(size_t)INNER_ * D_];
__device__ float  g_pacc[(size_t)SPLITS * B_ * N_ * INNER_];
__device__ float  g_pl  [(size_t)SPLITS * B_ * N_ * H_];

// ---------------- PTX helpers (plain sm_103-legal) ---------------------------
__device__ __forceinline__ unsigned su32(const void* p) {
    unsigned a;
    asm("{ .reg .u64 t; cvta.to.shared.u64 t, %1; cvt.u32.u64 %0, t; }"
        : "=r"(a) : "l"(p));
    return a;
}

#define CPA16(saddr, gptr) \
    asm volatile("cp.async.cg.shared.global [%0], [%1], 16;" \
                 :: "r"(saddr), "l"(gptr))
#define CPA_COMMIT() asm volatile("cp.async.commit_group;" ::: "memory")
#define CPA_WAIT1()  asm volatile("cp.async.wait_group 1;" ::: "memory")
#define CPA_WAIT0()  asm volatile("cp.async.wait_group 0;" ::: "memory")

#define LDSM4(r, addr) \
    asm volatile("ldmatrix.sync.aligned.m8n8.x4.shared.b16 {%0,%1,%2,%3}, [%4];" \
        : "=r"((r)[0]), "=r"((r)[1]), "=r"((r)[2]), "=r"((r)[3]) : "r"(addr))

#define MMA16816(c, a, b0, b1) \
    asm volatile("mma.sync.aligned.m16n8k16.row.col.f32.f16.f16.f32 " \
        "{%0,%1,%2,%3}, {%4,%5,%6,%7}, {%8,%9}, {%0,%1,%2,%3};" \
        : "+f"((c)[0]), "+f"((c)[1]), "+f"((c)[2]), "+f"((c)[3]) \
        : "r"((a)[0]), "r"((a)[1]), "r"((a)[2]), "r"((a)[3]), "r"(b0), "r"(b1))

// f32x2 packed fma (sm_103a)
#define FMA2(d, a, b, c) \
    asm("fma.rn.f32x2 %0, %1, %2, %3;" : "=l"(d) : "l"(a), "l"(b), "l"(c))

// ---------------------------------------------------------------------------
// LayerNorm -> fp16 hi/lo (kvin layout + optional compact latent copy)
// ---------------------------------------------------------------------------
__global__ void __launch_bounds__(256) ln_kernel(
    const float* __restrict__ x, const float* __restrict__ g,
    const float* __restrict__ be,
    __half* __restrict__ hi, __half* __restrict__ lo,
    int rpb, int base,
    __half* __restrict__ hi2, __half* __restrict__ lo2)
{
    int row = blockIdx.x;
    int tid = threadIdx.x;

    const float4* xr = reinterpret_cast<const float4*>(x) + (size_t)row * 256;
    float4 v = xr[tid];
    float s  = v.x + v.y + v.z + v.w;
    float ss = v.x * v.x + v.y * v.y + v.z * v.z + v.w * v.w;
    #pragma unroll
    for (int o = 16; o > 0; o >>= 1) {
        s  += __shfl_xor_sync(0xffffffffu, s,  o);
        ss += __shfl_xor_sync(0xffffffffu, ss, o);
    }
    __shared__ float ssum[8], ssq[8], sstat[2];
    int wid = tid >> 5, lid = tid & 31;
    if (lid == 0) { ssum[wid] = s; ssq[wid] = ss; }
    __syncthreads();
    if (tid == 0) {
        float a = 0.f, q2 = 0.f;
        #pragma unroll
        for (int i = 0; i < 8; i++) { a += ssum[i]; q2 += ssq[i]; }
        float mu  = a * (1.0f / 1024.0f);
        float var = q2 * (1.0f / 1024.0f) - mu * mu;
        sstat[0] = mu;
        sstat[1] = rsqrtf(var + 1e-5f);
    }
    __syncthreads();
    float mu = sstat[0], rs = sstat[1];

    float4 gv = reinterpret_cast<const float4*>(g)[tid];
    float4 bv = reinterpret_cast<const float4*>(be)[tid];
    float o0 = (v.x - mu) * rs * gv.x + bv.x;
    float o1 = (v.y - mu) * rs * gv.y + bv.y;
    float o2 = (v.z - mu) * rs * gv.z + bv.z;
    float o3 = (v.w - mu) * rs * gv.w + bv.w;

    __half h0 = __float2half_rn(o0);
    __half h1 = __float2half_rn(o1);
    __half h2 = __float2half_rn(o2);
    __half h3 = __float2half_rn(o3);
    __half l0 = __float2half_rn(o0 - __half2float(h0));
    __half l1 = __float2half_rn(o1 - __half2float(h1));
    __half l2 = __float2half_rn(o2 - __half2float(h2));
    __half l3 = __float2half_rn(o3 - __half2float(h3));
    __half2 hp0 = __halves2half2(h0, h1), hp1 = __halves2half2(h2, h3);
    __half2 lp0 = __halves2half2(l0, l1), lp1 = __halves2half2(l2, l3);

    int b = row / rpb;
    int r = row - b * rpb;
    size_t off = ((size_t)b * J_ + base + r) * 1024 + tid * 4;
    *reinterpret_cast<__half2*>(hi + off)     = hp0;
    *reinterpret_cast<__half2*>(hi + off + 2) = hp1;
    *reinterpret_cast<__half2*>(lo + off)     = lp0;
    *reinterpret_cast<__half2*>(lo + off + 2) = lp1;
    if (hi2) {
        size_t o2f = (size_t)row * 1024 + tid * 4;
        *reinterpret_cast<__half2*>(hi2 + o2f)     = hp0;
        *reinterpret_cast<__half2*>(hi2 + o2f + 2) = hp1;
        *reinterpret_cast<__half2*>(lo2 + o2f)     = lp0;
        *reinterpret_cast<__half2*>(lo2 + o2f + 2) = lp1;
    }
}

// ---------------------------------------------------------------------------
// Weight transpose + hi/lo fp16 convert: W[K][Nd] -> T{h,l}[Nd][K]
// ---------------------------------------------------------------------------
__global__ void __launch_bounds__(256) convT(
    const float* __restrict__ W, __half* __restrict__ Th,
    __half* __restrict__ Tl, int Kdim, int Ndim)
{
    __shared__ float s[32][33];
    int n0 = blockIdx.x * 32, k0 = blockIdx.y * 32;
    int tx = threadIdx.x & 31, ty = threadIdx.x >> 5;
    #pragma unroll
    for (int i = 0; i < 4; i++) {
        int k = k0 + ty + i * 8;
        s[ty + i * 8][tx] = W[(size_t)k * Ndim + n0 + tx];
    }
    __syncthreads();
    #pragma unroll
    for (int i = 0; i < 4; i++) {
        int n = n0 + ty + i * 8;
        float v = s[tx][ty + i * 8];
        __half h = __float2half_rn(v);
        __half l = __float2half_rn(v - __half2float(h));
        Th[(size_t)n * Kdim + k0 + tx] = h;
        Tl[(size_t)n * Kdim + k0 + tx] = l;
    }
}

// ---------------------------------------------------------------------------
// mma.sync GEMM: C = A @ B^T, fp16 hi/lo, fp32 acc.
//   Block tile 128x128, BK=32, 8 warps (4m x 2n), warp tile 32x64.
//   2-stage cp.async pipeline (smem 81920 B) + <=128 regs -> 2 CTAs/SM,
//   which is what fills the HMMA pipe (R13 measured 51% tensor at 1 CTA/SM).
//   Pass count: col < split_col -> 2-pass (hh+hl); else 3-pass (+lh).
// ---------------------------------------------------------------------------
#define NKT   32
#define ROWB  80
#define MATB  (128 * ROWB)     // 10240 B per matrix tile
#define STGB  (4 * MATB)       // 40960 B per stage (Ah, Al, Bh, Bl)
#define GSMEM (2 * STGB)       // 81920 B

__global__ void __launch_bounds__(256, 2) gemm_mma(
    const __half* __restrict__ Ah, const __half* __restrict__ Al,
    const __half* __restrict__ Bh, const __half* __restrict__ Bl,
    float* __restrict__ C, int ldc, int split_col)
{
    extern __shared__ char smem[];
    const int tid  = threadIdx.x;
    const int lane = tid & 31, wid = tid >> 5;
    const int wm = wid & 3, wn = wid >> 2;          // 4 x 2 warps

    const size_t arow0 = (size_t)blockIdx.y * 128;
    const size_t bcol0 = (size_t)blockIdx.x * 128;
    const bool use3 = ((int)bcol0 >= split_col);

    const __half* src0 = Ah + arow0 * 1024;
    const __half* src1 = Al + arow0 * 1024;
    const __half* src2 = Bh + bcol0 * 1024;
    const __half* src3 = Bl + bcol0 * 1024;

    const unsigned smbase = su32(smem);

    // loader mapping: thread -> 2 16B chunks per matrix (128 rows x 4 chunks)
    const int q0   = tid * 2;
    const int lrow = q0 >> 2;            // 0..127
    const int c0   = q0 & 3;             // 0 or 2
    const unsigned sof0 = (unsigned)(lrow * ROWB + c0 * 16);
    const unsigned sof1 = sof0 + 16;
    const size_t   gof0 = (size_t)lrow * 1024 + c0 * 8;

    // ldmatrix per-lane offsets
    const unsigned rbA = (unsigned)((wm * 32 + (lane & 15)) * ROWB);
    const unsigned hiA = (unsigned)(lane >> 4);
    const unsigned rbB = (unsigned)((wn * 64 + ((lane >> 4) << 3) + (lane & 7)) * ROWB);
    const unsigned hiB = (unsigned)((lane >> 3) & 1);

    float acc[2][8][4];
    #pragma unroll
    for (int i = 0; i < 2; i++)
        #pragma unroll
        for (int j = 0; j < 8; j++)
            #pragma unroll
            for (int k = 0; k < 4; k++) acc[i][j][k] = 0.f;

    auto load_stage = [&](int st, int kt) {
        unsigned sb = smbase + st * STGB;
        const __half* s;
        s = src0 + (size_t)kt * 32;
        CPA16(sb + sof0,            s + gof0);
        CPA16(sb + sof1,            s + gof0 + 8);
        if (use3) {
            s = src1 + (size_t)kt * 32;
            CPA16(sb + MATB + sof0, s + gof0);
            CPA16(sb + MATB + sof1, s + gof0 + 8);
        }
        s = src2 + (size_t)kt * 32;
        CPA16(sb + 2 * MATB + sof0, s + gof0);
        CPA16(sb + 2 * MATB + sof1, s + gof0 + 8);
        s = src3 + (size_t)kt * 32;
        CPA16(sb + 3 * MATB + sof0, s + gof0);
        CPA16(sb + 3 * MATB + sof1, s + gof0 + 8);
    };

    load_stage(0, 0);
    CPA_COMMIT();

    for (int kt = 0; kt < NKT; kt++) {
        int cur = kt & 1;
        if (kt + 1 < NKT) {
            load_stage(cur ^ 1, kt + 1);
            CPA_COMMIT();
            CPA_WAIT1();
        } else {
            CPA_WAIT0();
        }
        __syncthreads();

        unsigned base = smbase + cur * STGB;
        #pragma unroll
        for (int ks = 0; ks < 2; ks++) {
            unsigned ah[2][4], al[2][4];
            unsigned chA = (unsigned)((ks * 2 + hiA) << 4);
            unsigned chB = (unsigned)((ks * 2 + hiB) << 4);
            #pragma unroll
            for (int mi = 0; mi < 2; mi++) {
                unsigned ra = rbA + mi * (16 * ROWB);
                LDSM4(ah[mi], base + ra + chA);
                if (use3) LDSM4(al[mi], base + MATB + ra + chA);
            }
            // B fragments loaded per-nb: keeps live regs low (2 CTAs/SM)
            #pragma unroll
            for (int nb = 0; nb < 4; nb++) {
                unsigned bh4[4], bl4[4];
                unsigned rb = rbB + nb * (16 * ROWB);
                LDSM4(bh4, base + 2 * MATB + rb + chB);
                LDSM4(bl4, base + 3 * MATB + rb + chB);
                #pragma unroll
                for (int mi = 0; mi < 2; mi++) {
                    MMA16816(acc[mi][nb * 2],     ah[mi], bh4[0], bh4[1]);  // hh
                    MMA16816(acc[mi][nb * 2 + 1], ah[mi], bh4[2], bh4[3]);
                    MMA16816(acc[mi][nb * 2],     ah[mi], bl4[0], bl4[1]);  // hl
                    MMA16816(acc[mi][nb * 2 + 1], ah[mi], bl4[2], bl4[3]);
                    if (use3) {
                        MMA16816(acc[mi][nb * 2],     al[mi], bh4[0], bh4[1]);  // lh
                        MMA16816(acc[mi][nb * 2 + 1], al[mi], bh4[2], bh4[3]);
                    }
                }
            }
        }
        __syncthreads();
    }

    // epilogue
    const int lr  = lane >> 2;
    const int lc2 = (lane & 3) * 2;
    #pragma unroll
    for (int mi = 0; mi < 2; mi++) {
        size_t r0 = arow0 + wm * 32 + mi * 16 + lr;
        #pragma unroll
        for (int ni = 0; ni < 8; ni++) {
            size_t col = bcol0 + wn * 64 + ni * 8 + lc2;
            *reinterpret_cast<float2*>(C + r0 * ldc + col) =
                make_float2(acc[mi][ni][0], acc[mi][ni][1]);
            *reinterpret_cast<float2*>(C + (r0 + 8) * ldc + col) =
                make_float2(acc[mi][ni][2], acc[mi][ni][3]);
        }
    }
}

// ---------------------------------------------------------------------------
// Attention (split-KV, packed f32x2 FMAs). Block = (h, b, split); thread = n.
// p = exp(q.k) * mask  (rowmax and the +1 additive constant cancel in softmax)
// ---------------------------------------------------------------------------
__global__ void __launch_bounds__(256, 1) attn_kernel(
    const float* __restrict__ q, const float* __restrict__ kv,
    const int* __restrict__ mask, float* __restrict__ pacc,
    float* __restrict__ pl)
{
    int h = blockIdx.x, b = blockIdx.y, sp = blockIdx.z;
    int tid = threadIdx.x;

    __shared__ alignas(16) float k_s[64][64];
    __shared__ alignas(16) float v_s[64][64];
    __shared__ float m_s[64];

    unsigned long long qp[32], ap[32];
    const float* qrow = q + (size_t)(b * N_ + tid) * INNER_ + h * 64;
    #pragma unroll
    for (int d = 0; d < 16; d++) {
        float4 t = reinterpret_cast<const float4*>(qrow)[d];
        t.x *= 0.125f; t.y *= 0.125f; t.z *= 0.125f; t.w *= 0.125f;
        asm("mov.b64 %0, {%1, %2};" : "=l"(qp[2 * d])     : "f"(t.x), "f"(t.y));
        asm("mov.b64 %0, {%1, %2};" : "=l"(qp[2 * d + 1]) : "f"(t.z), "f"(t.w));
    }
    #pragma unroll
    for (int i = 0; i < 32; i++) ap[i] = 0ull;
    float l = 0.f;

    const size_t kvbase = (size_t)b * J_ * 2048 + (size_t)h * 64;

    for (int j0 = sp * JSPLIT; j0 < (sp + 1) * JSPLIT; j0 += 64) {
        #pragma unroll
        for (int t = 0; t < 4; t++) {
            int idx = tid + t * 256;
            int r = idx >> 4, c = (idx & 15) << 2;
            size_t g = kvbase + (size_t)(j0 + r) * 2048 + c;
            *reinterpret_cast<float4*>(&k_s[r][c]) = *reinterpret_cast<const float4*>(kv + g);
            *reinterpret_cast<float4*>(&v_s[r][c]) = *reinterpret_cast<const float4*>(kv + g + 1024);
        }
        if (tid < 64) {
            int j = j0 + tid;
            m_s[tid] = (j < M_) ? (mask[b * M_ + j] ? 0.f : 1.f) : 1.f;
        }
        __syncthreads();

        #pragma unroll 1
        for (int jj = 0; jj < 64; jj++) {
            const ulonglong2* kr = reinterpret_cast<const ulonglong2*>(&k_s[jj][0]);
            unsigned long long a0 = 0ull, a1 = 0ull, a2 = 0ull, a3 = 0ull;
            #pragma unroll
            for (int i = 0; i < 16; i += 2) {
                ulonglong2 kA = kr[i], kB = kr[i + 1];
                FMA2(a0, qp[2 * i],     kA.x, a0);
                FMA2(a1, qp[2 * i + 1], kA.y, a1);
                FMA2(a2, qp[2 * i + 2], kB.x, a2);
                FMA2(a3, qp[2 * i + 3], kB.y, a3);
            }
            float f0, f1, f2, f3, f4, f5, f6, f7;
            asm("mov.b64 {%0,%1}, %2;" : "=f"(f0), "=f"(f1) : "l"(a0));
            asm("mov.b64 {%0,%1}, %2;" : "=f"(f2), "=f"(f3) : "l"(a1));
            asm("mov.b64 {%0,%1}, %2;" : "=f"(f4), "=f"(f5) : "l"(a2));
            asm("mov.b64 {%0,%1}, %2;" : "=f"(f6), "=f"(f7) : "l"(a3));
            float p = __expf(((f0 + f1) + (f2 + f3)) + ((f4 + f5) + (f6 + f7))) * m_s[jj];
            l += p;
            unsigned long long pp;
            asm("mov.b64 %0, {%1, %1};" : "=l"(pp) : "f"(p));
            const ulonglong2* vr = reinterpret_cast<const ulonglong2*>(&v_s[jj][0]);
            #pragma unroll
            for (int i = 0; i < 16; i++) {
                ulonglong2 vv = vr[i];
                FMA2(ap[2 * i],     pp, vv.x, ap[2 * i]);
                FMA2(ap[2 * i + 1], pp, vv.y, ap[2 * i + 1]);
            }
        }
        __syncthreads();
    }

    unsigned long long* op = reinterpret_cast<unsigned long long*>(
        pacc + ((size_t)((sp * B_ + b) * N_ + tid)) * INNER_ + h * 64);
    #pragma unroll
    for (int i = 0; i < 32; i++) op[i] = ap[i];
    pl[((size_t)(sp * B_ + b) * N_ + tid) * H_ + h] = l;
}

// ---------------------------------------------------------------------------
// Merge split-KV partials -> fp16 hi/lo for the Wo GEMM. grid=2048 rows.
// ---------------------------------------------------------------------------
__global__ void __launch_bounds__(256) merge_kernel(
    const float* __restrict__ pacc, const float* __restrict__ pl,
    __half* __restrict__ oh, __half* __restrict__ ol)
{
    int row = blockIdx.x;
    int tid = threadIdx.x;
    int col = tid * 4;
    int h = col >> 6;

    float lsum = 0.f;
    #pragma unroll
    for (int sp = 0; sp < SPLITS; sp++)
        lsum += pl[((size_t)(sp * (B_ * N_) + row)) * H_ + h];

    float4 a = make_float4(0.f, 0.f, 0.f, 0.f);
    #pragma unroll
    for (int sp = 0; sp < SPLITS; sp++) {
        float4 t = *reinterpret_cast<const float4*>(
            pacc + ((size_t)(sp * (B_ * N_) + row)) * 1024 + col);
        a.x += t.x; a.y += t.y; a.z += t.z; a.w += t.w;
    }
    float inv = 1.f / lsum;
    a.x *= inv; a.y *= inv; a.z *= inv; a.w *= inv;

    __half h0 = __float2half_rn(a.x);
    __half h1 = __float2half_rn(a.y);
    __half h2 = __float2half_rn(a.z);
    __half h3 = __float2half_rn(a.w);
    __half l0 = __float2half_rn(a.x - __half2float(h0));
    __half l1 = __float2half_rn(a.y - __half2float(h1));
    __half l2 = __float2half_rn(a.z - __half2float(h2));
    __half l3 = __float2half_rn(a.w - __half2float(h3));

    size_t off = (size_t)row * 1024 + col;
    *reinterpret_cast<__half2*>(oh + off)     = __halves2half2(h0, h1);
    *reinterpret_cast<__half2*>(oh + off + 2) = __halves2half2(h2, h3);
    *reinterpret_cast<__half2*>(ol + off)     = __halves2half2(l0, l1);
    *reinterpret_cast<__half2*>(ol + off + 2) = __halves2half2(l2, l3);
}

// ---------------------------------------------------------------------------
extern "C" void kernel_launch(void* const* d_in, const int* in_sizes, int n_in,
                              void* d_out, int out_size)
{
    const float* x       = (const float*)d_in[0];
    const float* latents = (const float*)d_in[1];
    const int*   xmask   = (const int*)  d_in[2];
    const float* nm_g    = (const float*)d_in[3];
    const float* nm_b    = (const float*)d_in[4];
    const float* nl_g    = (const float*)d_in[5];
    const float* nl_b    = (const float*)d_in[6];
    const float* Wq      = (const float*)d_in[7];
    const float* Wkv     = (const float*)d_in[8];
    const float* Wo      = (const float*)d_in[9];
    float*       out     = (float*)d_out;

    __half *ah, *al, *lath, *latl, *atth, *attl;
    __half *wkvh, *wkvl, *wqh, *wql, *woh, *wol;
    float *kvb, *qb, *pacc, *pl;
    cudaGetSymbolAddress((void**)&ah,   g_ah);
    cudaGetSymbolAddress((void**)&al,   g_al);
    cudaGetSymbolAddress((void**)&lath, g_lath);
    cudaGetSymbolAddress((void**)&latl, g_latl);
    cudaGetSymbolAddress((void**)&kvb,  g_kv);
    cudaGetSymbolAddress((void**)&qb,   g_q);
    cudaGetSymbolAddress((void**)&atth, g_atth);
    cudaGetSymbolAddress((void**)&attl, g_attl);
    cudaGetSymbolAddress((void**)&wkvh, g_wkvh);
    cudaGetSymbolAddress((void**)&wkvl, g_wkvl);
    cudaGetSymbolAddress((void**)&wqh,  g_wqh);
    cudaGetSymbolAddress((void**)&wql,  g_wql);
    cudaGetSymbolAddress((void**)&woh,  g_woh);
    cudaGetSymbolAddress((void**)&wol,  g_wol);
    cudaGetSymbolAddress((void**)&pacc, g_pacc);
    cudaGetSymbolAddress((void**)&pl,   g_pl);

    cudaFuncSetAttribute(gemm_mma, cudaFuncAttributeMaxDynamicSharedMemorySize, GSMEM);

    // Order chosen so the fixed ncu window (-s 5 -c 1) lands near gemm_kv.
    convT<<<dim3(2048 / 32, 1024 / 32), 256>>>(Wkv, wkvh, wkvl, 1024, 2048);
    ln_kernel<<<B_ * M_, 256>>>(x,       nm_g, nm_b, ah, al, M_, 0,  nullptr, nullptr);
    ln_kernel<<<B_ * N_, 256>>>(latents, nl_g, nl_b, ah, al, N_, M_, lath,    latl);

    // kv = kvin @ Wkv : cols [0,1024) = K (2-pass), cols [1024,2048) = V (3-pass)
    gemm_mma<<<dim3(2048 / 128, (B_ * J_) / 128), 256, GSMEM>>>(
        ah, al, wkvh, wkvl, kvb, 2048, 1024);

    // q = ln(latents) @ Wq : all 2-pass (feeds scores only)
    convT<<<dim3(1024 / 32, 1024 / 32), 256>>>(Wq, wqh, wql, 1024, 1024);
    gemm_mma<<<dim3(1024 / 128, (B_ * N_) / 128), 256, GSMEM>>>(
        lath, latl, wqh, wql, qb, 1024, 1 << 30);

    // attention (split-KV) + merge
    attn_kernel<<<dim3(H_, B_, SPLITS), 256>>>(qb, kvb, xmask, pacc, pl);
    merge_kernel<<<B_ * N_, 256>>>(pacc, pl, atth, attl);

    // out = att @ Wo : 3-pass everywhere (direct output path)
    convT<<<dim3(1024 / 32, 1024 / 32), 256>>>(Wo, woh, wol, 1024, 1024);
    gemm_mma<<<dim3(1024 / 128, (B_ * N_) / 128), 256, GSMEM>>>(
        atth, attl, woh, wol, out, 1024, 0);
}